// round 13
// baseline (speedup 1.0000x reference)
#include <cuda_runtime.h>
#include <cuda_fp16.h>
#include <cstdint>
#include <math.h>

#define E_NUM 8
#define D_DIM 1024
#define H_DIM 1024
#define H2    2048
#define NTOK  2048
#define NPAIR 4096

// ----------------------------- scratch globals ------------------------------
__device__ int g_pairs[NPAIR];
__device__ int g_cnt[E_NUM];
__device__ int g_off[E_NUM];
__device__ __half g_x[(size_t)NTOK * D_DIM];                // by TOKEN
__device__ __half g_w1_hi[(size_t)E_NUM * D_DIM * H2];      // [E][k=D][n=2H]
__device__ __half g_w2_hi[(size_t)E_NUM * H_DIM * D_DIM];   // [E][k=H][n=D]
__device__ __half g_act[(size_t)NPAIR * H_DIM];             // by sorted SLOT

// ------------------------------ helpers -------------------------------------
__device__ __forceinline__ uint32_t smem_u32(const void* p) {
    uint32_t a;
    asm("{ .reg .u64 t; cvta.to.shared.u64 t, %1; cvt.u32.u64 %0, t; }"
        : "=r"(a) : "l"(p));
    return a;
}
__device__ __forceinline__ void cp16(uint32_t dst, const void* src) {
    asm volatile("cp.async.cg.shared.global [%0], [%1], 16;"
                 :: "r"(dst), "l"(src) : "memory");
}
#define CP_COMMIT() asm volatile("cp.async.commit_group;" ::: "memory")
#define CP_WAIT(n)  asm volatile("cp.async.wait_group %0;" :: "n"(n) : "memory")

__device__ __forceinline__ void ldsm4(uint32_t* r, uint32_t a) {
    asm volatile("ldmatrix.sync.aligned.m8n8.x4.shared.b16 {%0,%1,%2,%3}, [%4];"
                 : "=r"(r[0]), "=r"(r[1]), "=r"(r[2]), "=r"(r[3]) : "r"(a));
}
__device__ __forceinline__ void ldsm4t(uint32_t* r, uint32_t a) {
    asm volatile("ldmatrix.sync.aligned.m8n8.x4.trans.shared.b16 {%0,%1,%2,%3}, [%4];"
                 : "=r"(r[0]), "=r"(r[1]), "=r"(r[2]), "=r"(r[3]) : "r"(a));
}
__device__ __forceinline__ void mma16816(float* d, const uint32_t* a, const uint32_t* b) {
    asm volatile(
        "mma.sync.aligned.m16n8k16.row.col.f32.f16.f16.f32 "
        "{%0,%1,%2,%3}, {%4,%5,%6,%7}, {%8,%9}, {%0,%1,%2,%3};"
        : "+f"(d[0]), "+f"(d[1]), "+f"(d[2]), "+f"(d[3])
        : "r"(a[0]), "r"(a[1]), "r"(a[2]), "r"(a[3]), "r"(b[0]), "r"(b[1]));
}
__device__ __forceinline__ uint32_t pack_h2(__half a, __half b) {
    return ((uint32_t)__half_as_ushort(b) << 16) | (uint32_t)__half_as_ushort(a);
}
__device__ __forceinline__ float silu_mul(float h, float g) {
    return h * (g / (1.f + __expf(-g)));
}

// SMEM: rows_s[128] ints @0; stages @512.
// Stage (K-chunk 64): A [128m][64k] pitch 144 | B [64k][64n] pitch 144. 2 stages.
#define A_PITCH  144
#define B_PITCH  144
#define OFF_A    0
#define OFF_B    (128 * A_PITCH)
#define STAGE_SZ (128 * A_PITCH + 64 * B_PITCH)     // 27648
#define NSTAGE   2
#define SMEM_DYN (512 + NSTAGE * STAGE_SZ)          // 55808 (x3 CTAs = 167.4KB/SM)
#define KCH      64
#define NITER    (D_DIM / KCH)                      // 16 (same for H_DIM)

// ---------------------------------------------------------------------------
// Kernel 0: bucket pairs by expert (single CTA)
// ---------------------------------------------------------------------------
__global__ void bucket_kernel(const int* __restrict__ expert_idxs) {
    __shared__ int scnt[E_NUM];
    __shared__ int soff[E_NUM];
    __shared__ int spos[E_NUM];
    int tid = threadIdx.x;
    if (tid < E_NUM) scnt[tid] = 0;
    __syncthreads();
    for (int i = tid; i < NPAIR; i += blockDim.x)
        atomicAdd(&scnt[expert_idxs[i]], 1);
    __syncthreads();
    if (tid == 0) {
        int s = 0;
        for (int e = 0; e < E_NUM; e++) { soff[e] = s; spos[e] = s; s += scnt[e]; }
    }
    __syncthreads();
    for (int i = tid; i < NPAIR; i += blockDim.x) {
        int e = expert_idxs[i];
        int pos = atomicAdd(&spos[e], 1);
        g_pairs[pos] = i;
    }
    __syncthreads();
    if (tid < E_NUM) { g_cnt[tid] = scnt[tid]; g_off[tid] = soff[tid]; }
}

// ---------------------------------------------------------------------------
// Kernel 1: zero the output (poisoned by harness; atomics accumulate into it)
// ---------------------------------------------------------------------------
__global__ void zero_out_kernel(float* __restrict__ out) {
    int q = blockIdx.x * blockDim.x + threadIdx.x;
    ((float4*)out)[q] = make_float4(0.f, 0.f, 0.f, 0.f);
}

// ---------------------------------------------------------------------------
// Kernel 2: fused fp32->fp16 conversion of x, W1, W2 (8 floats / thread)
// ---------------------------------------------------------------------------
#define X8   (NTOK * D_DIM / 8)
#define W18  (E_NUM * D_DIM * H2 / 8)
#define W28  (E_NUM * H_DIM * D_DIM / 8)
#define CONV_TOTAL (X8 + W18 + W28)

__global__ void conv_all_kernel(const float* __restrict__ x,
                                const float* __restrict__ W1,
                                const float* __restrict__ W2) {
    int idx = blockIdx.x * blockDim.x + threadIdx.x;
    const float4* src;
    __half* dst;
    if (idx < X8) {
        src = (const float4*)x + (size_t)idx * 2;
        dst = g_x + (size_t)idx * 8;
    } else if (idx < X8 + W18) {
        int j = idx - X8;
        src = (const float4*)W1 + (size_t)j * 2;
        dst = g_w1_hi + (size_t)j * 8;
    } else {
        int j = idx - (X8 + W18);
        src = (const float4*)W2 + (size_t)j * 2;
        dst = g_w2_hi + (size_t)j * 8;
    }
    float4 a = src[0], b = src[1];
    uint4 o;
    o.x = pack_h2(__float2half_rn(a.x), __float2half_rn(a.y));
    o.y = pack_h2(__float2half_rn(a.z), __float2half_rn(a.w));
    o.z = pack_h2(__float2half_rn(b.x), __float2half_rn(b.y));
    o.w = pack_h2(__float2half_rn(b.z), __float2half_rn(b.w));
    *(uint4*)dst = o;
}

// ---------------------------------------------------------------------------
// GEMM1 (mma.sync fp16, occ=3, warp tile 32x32): act = h * silu(g)
//   CTA 128m x (32h + 32g cols). 8 warps = wm(4) x wc(2); warp 32m x (16h+16g).
//   grid = (H/32, NPAIR/128, E)
// ---------------------------------------------------------------------------
__global__ void __launch_bounds__(256, 3) gemm1_mma() {
    extern __shared__ char smem[];
    const int e   = blockIdx.z;
    const int bn  = blockIdx.x;
    const int bm  = blockIdx.y;
    const int cnt = g_cnt[e];
    if (bm * 128 >= cnt) return;
    const int off = g_off[e];
    const int tid = threadIdx.x;
    const int wid = tid >> 5;
    const int l   = tid & 31;
    const int wm  = wid >> 1;
    const int wc  = wid & 1;

    int* rows_s = (int*)smem;
    const uint32_t sbase = smem_u32(smem) + 512;

    if (tid < 128) {
        int m = bm * 128 + tid;
        rows_s[tid] = (m < cnt) ? (g_pairs[off + m] >> 1) : 0;
    }
    __syncthreads();

    uint32_t a_base[2];
#pragma unroll
    for (int mt = 0; mt < 2; mt++)
        a_base[mt] = (wm * 32 + mt * 16 + (l & 15)) * A_PITCH + (l >> 4) * 16;
    // p=0: h cols [wc*16, +16); p=1: g cols [32 + wc*16, +16)
    uint32_t b_base[2];
#pragma unroll
    for (int p = 0; p < 2; p++) {
        int colbase = p * 32 + wc * 16;
        b_base[p] = (l & 15) * B_PITCH + (colbase + (l >> 4) * 8) * 2;
    }

    float acc[2][4][4];
#pragma unroll
    for (int mt = 0; mt < 2; mt++)
#pragma unroll
        for (int nt = 0; nt < 4; nt++)
#pragma unroll
            for (int i = 0; i < 4; i++) acc[mt][nt][i] = 0.f;

    auto load_stage = [&](int c, int buf) {
        const int kt = c * KCH;
        const uint32_t st = sbase + buf * STAGE_SZ;
        // A: 128 rows x 128B = 1024 cp16
#pragma unroll
        for (int i = 0; i < 4; i++) {
            int q = tid + i * 256;
            int r = q >> 3, ch = q & 7;
            cp16(st + OFF_A + r * A_PITCH + ch * 16,
                 g_x + (size_t)rows_s[r] * D_DIM + kt + ch * 8);
        }
        // B: 64 k-rows x 128B = 512 cp16; ch<4 -> h cols, ch>=4 -> g cols
#pragma unroll
        for (int i = 0; i < 2; i++) {
            int q = tid + i * 256;
            int r = q >> 3, ch = q & 7;
            int gcol = (ch < 4) ? (bn * 32 + ch * 8) : (H_DIM + bn * 32 + (ch - 4) * 8);
            cp16(st + OFF_B + r * B_PITCH + ch * 16,
                 g_w1_hi + ((size_t)e * D_DIM + kt + r) * H2 + gcol);
        }
        CP_COMMIT();
    };

    load_stage(0, 0);

    for (int c = 0; c < NITER; c++) {
        CP_WAIT(0);
        __syncthreads();
        if (c + 1 < NITER) load_stage(c + 1, (c + 1) & 1);
        const uint32_t st = sbase + (c & 1) * STAGE_SZ;
#pragma unroll
        for (int kk = 0; kk < 4; kk++) {
            uint32_t ah[2][4], bf[2][4];
#pragma unroll
            for (int mt = 0; mt < 2; mt++)
                ldsm4(ah[mt], st + OFF_A + a_base[mt] + kk * 32);
#pragma unroll
            for (int p = 0; p < 2; p++)
                ldsm4t(bf[p], st + OFF_B + b_base[p] + kk * (16 * B_PITCH));
#pragma unroll
            for (int mt = 0; mt < 2; mt++)
#pragma unroll
                for (int nt = 0; nt < 4; nt++)
                    mma16816(acc[mt][nt], ah[mt], &bf[nt >> 1][(nt & 1) * 2]);
        }
    }

    // ---- epilogue: pair h (nt) with g (nt+2), SiLU-GLU, store fp16 ----
#pragma unroll
    for (int mt = 0; mt < 2; mt++) {
        int m0 = bm * 128 + wm * 32 + mt * 16 + (l >> 2);
        int m1 = m0 + 8;
        bool v0 = (m0 < cnt), v1 = (m1 < cnt);
        size_t row0 = (size_t)(off + m0) * H_DIM;
        size_t row1 = (size_t)(off + m1) * H_DIM;
#pragma unroll
        for (int nt = 0; nt < 2; nt++) {
            int col = bn * 32 + wc * 16 + nt * 8 + 2 * (l & 3);
            float a0 = silu_mul(acc[mt][nt][0], acc[mt][nt + 2][0]);
            float a1 = silu_mul(acc[mt][nt][1], acc[mt][nt + 2][1]);
            float a2 = silu_mul(acc[mt][nt][2], acc[mt][nt + 2][2]);
            float a3 = silu_mul(acc[mt][nt][3], acc[mt][nt + 2][3]);
            if (v0)
                *(uint32_t*)(g_act + row0 + col) =
                    pack_h2(__float2half_rn(a0), __float2half_rn(a1));
            if (v1)
                *(uint32_t*)(g_act + row1 + col) =
                    pack_h2(__float2half_rn(a2), __float2half_rn(a3));
        }
    }
}

// ---------------------------------------------------------------------------
// GEMM2 (mma.sync fp16, occ=3, warp tile 32x32): out += (act @ W2) * p
//   CTA 128m x 64n. grid = (D/64, NPAIR/128, E). Atomic accumulate (2/elem).
// ---------------------------------------------------------------------------
__global__ void __launch_bounds__(256, 3) gemm2_mma(const float* __restrict__ expert_p,
                                                    float* __restrict__ out) {
    extern __shared__ char smem[];
    const int e   = blockIdx.z;
    const int bn  = blockIdx.x;
    const int bm  = blockIdx.y;
    const int cnt = g_cnt[e];
    if (bm * 128 >= cnt) return;
    const int off = g_off[e];
    const int tid = threadIdx.x;
    const int wid = tid >> 5;
    const int l   = tid & 31;
    const int wm  = wid >> 1;
    const int wc  = wid & 1;

    const uint32_t sbase = smem_u32(smem) + 512;

    uint32_t a_base[2];
#pragma unroll
    for (int mt = 0; mt < 2; mt++)
        a_base[mt] = (wm * 32 + mt * 16 + (l & 15)) * A_PITCH + (l >> 4) * 16;
    uint32_t b_base[2];
#pragma unroll
    for (int p = 0; p < 2; p++) {
        int colbase = wc * 32 + p * 16;
        b_base[p] = (l & 15) * B_PITCH + (colbase + (l >> 4) * 8) * 2;
    }

    float acc[2][4][4];
#pragma unroll
    for (int mt = 0; mt < 2; mt++)
#pragma unroll
        for (int nt = 0; nt < 4; nt++)
#pragma unroll
            for (int i = 0; i < 4; i++) acc[mt][nt][i] = 0.f;

    auto load_stage = [&](int c, int buf) {
        const int kt = c * KCH;
        const uint32_t st = sbase + buf * STAGE_SZ;
#pragma unroll
        for (int i = 0; i < 4; i++) {
            int q = tid + i * 256;
            int r = q >> 3, ch = q & 7;
            int gr = off + bm * 128 + r;
            if (gr > NPAIR - 1) gr = NPAIR - 1;
            cp16(st + OFF_A + r * A_PITCH + ch * 16,
                 g_act + (size_t)gr * H_DIM + kt + ch * 8);
        }
#pragma unroll
        for (int i = 0; i < 2; i++) {
            int q = tid + i * 256;
            int r = q >> 3, ch = q & 7;
            cp16(st + OFF_B + r * B_PITCH + ch * 16,
                 g_w2_hi + ((size_t)e * H_DIM + kt + r) * D_DIM + bn * 64 + ch * 8);
        }
        CP_COMMIT();
    };

    load_stage(0, 0);

    for (int c = 0; c < NITER; c++) {
        CP_WAIT(0);
        __syncthreads();
        if (c + 1 < NITER) load_stage(c + 1, (c + 1) & 1);
        const uint32_t st = sbase + (c & 1) * STAGE_SZ;
#pragma unroll
        for (int kk = 0; kk < 4; kk++) {
            uint32_t ah[2][4], bf[2][4];
#pragma unroll
            for (int mt = 0; mt < 2; mt++)
                ldsm4(ah[mt], st + OFF_A + a_base[mt] + kk * 32);
#pragma unroll
            for (int p = 0; p < 2; p++)
                ldsm4t(bf[p], st + OFF_B + b_base[p] + kk * (16 * B_PITCH));
#pragma unroll
            for (int mt = 0; mt < 2; mt++)
#pragma unroll
                for (int nt = 0; nt < 4; nt++)
                    mma16816(acc[mt][nt], ah[mt], &bf[nt >> 1][(nt & 1) * 2]);
        }
    }

    // ---- epilogue: scale by gate prob, atomically accumulate into out ----
#pragma unroll
    for (int mt = 0; mt < 2; mt++) {
        int m0 = bm * 128 + wm * 32 + mt * 16 + (l >> 2);
        int m1 = m0 + 8;
        bool v0 = (m0 < cnt), v1 = (m1 < cnt);
        int   pid0 = 0, pid1 = 0;
        float pv0 = 0.f, pv1 = 0.f;
        if (v0) { pid0 = g_pairs[off + m0]; pv0 = expert_p[pid0]; }
        if (v1) { pid1 = g_pairs[off + m1]; pv1 = expert_p[pid1]; }
        float* dst0 = out + (size_t)(pid0 >> 1) * D_DIM;
        float* dst1 = out + (size_t)(pid1 >> 1) * D_DIM;
#pragma unroll
        for (int nt = 0; nt < 4; nt++) {
            int col = bn * 64 + wc * 32 + nt * 8 + 2 * (l & 3);
            if (v0) {
                atomicAdd(dst0 + col,     acc[mt][nt][0] * pv0);
                atomicAdd(dst0 + col + 1, acc[mt][nt][1] * pv0);
            }
            if (v1) {
                atomicAdd(dst1 + col,     acc[mt][nt][2] * pv1);
                atomicAdd(dst1 + col + 1, acc[mt][nt][3] * pv1);
            }
        }
    }
}

// ---------------------------------------------------------------------------
extern "C" void kernel_launch(void* const* d_in, const int* in_sizes, int n_in,
                              void* d_out, int out_size) {
    const float* x    = (const float*)d_in[0];
    const float* ep   = (const float*)d_in[1];
    const int*   eidx = (const int*)  d_in[2];
    const float* W1   = (const float*)d_in[3];
    const float* W2   = (const float*)d_in[4];
    float*       out  = (float*)d_out;

    cudaFuncSetAttribute(gemm1_mma, cudaFuncAttributeMaxDynamicSharedMemorySize, SMEM_DYN);
    cudaFuncSetAttribute(gemm2_mma, cudaFuncAttributeMaxDynamicSharedMemorySize, SMEM_DYN);

    bucket_kernel<<<1, 512>>>(eidx);
    zero_out_kernel<<<(NTOK * D_DIM / 4) / 256, 256>>>(out);

    conv_all_kernel<<<CONV_TOTAL / 256, 256>>>(x, W1, W2);

    dim3 g1(H_DIM / 32, NPAIR / 128, E_NUM);    // (32, 32, 8)
    gemm1_mma<<<g1, 256, SMEM_DYN>>>();

    dim3 g2(D_DIM / 64, NPAIR / 128, E_NUM);    // (16, 32, 8)
    gemm2_mma<<<g2, 256, SMEM_DYN>>>(ep, out);
}

// round 14
// speedup vs baseline: 1.3820x; 1.3820x over previous
#include <cuda_runtime.h>
#include <cuda_fp16.h>
#include <cstdint>
#include <math.h>

#define E_NUM 8
#define D_DIM 1024
#define H_DIM 1024
#define H2    2048
#define NTOK  2048
#define NPAIR 4096

// ----------------------------- scratch globals ------------------------------
__device__ int g_pairs[NPAIR];
__device__ int g_cnt[E_NUM];
__device__ int g_off[E_NUM];
__device__ __half g_x[(size_t)NTOK * D_DIM];                // by TOKEN
__device__ __half g_w1_hi[(size_t)E_NUM * D_DIM * H2];      // [E][k=D][n=2H]
__device__ __half g_w2_hi[(size_t)E_NUM * H_DIM * D_DIM];   // [E][k=H][n=D]
__device__ __half g_act[(size_t)NPAIR * H_DIM];             // by sorted SLOT

// ------------------------------ helpers -------------------------------------
__device__ __forceinline__ uint32_t smem_u32(const void* p) {
    uint32_t a;
    asm("{ .reg .u64 t; cvta.to.shared.u64 t, %1; cvt.u32.u64 %0, t; }"
        : "=r"(a) : "l"(p));
    return a;
}
__device__ __forceinline__ void cp16(uint32_t dst, const void* src) {
    asm volatile("cp.async.cg.shared.global [%0], [%1], 16;"
                 :: "r"(dst), "l"(src) : "memory");
}
#define CP_COMMIT() asm volatile("cp.async.commit_group;" ::: "memory")
#define CP_WAIT(n)  asm volatile("cp.async.wait_group %0;" :: "n"(n) : "memory")

__device__ __forceinline__ void ldsm4(uint32_t* r, uint32_t a) {
    asm volatile("ldmatrix.sync.aligned.m8n8.x4.shared.b16 {%0,%1,%2,%3}, [%4];"
                 : "=r"(r[0]), "=r"(r[1]), "=r"(r[2]), "=r"(r[3]) : "r"(a));
}
__device__ __forceinline__ void ldsm4t(uint32_t* r, uint32_t a) {
    asm volatile("ldmatrix.sync.aligned.m8n8.x4.trans.shared.b16 {%0,%1,%2,%3}, [%4];"
                 : "=r"(r[0]), "=r"(r[1]), "=r"(r[2]), "=r"(r[3]) : "r"(a));
}
__device__ __forceinline__ void mma16816(float* d, const uint32_t* a, const uint32_t* b) {
    asm volatile(
        "mma.sync.aligned.m16n8k16.row.col.f32.f16.f16.f32 "
        "{%0,%1,%2,%3}, {%4,%5,%6,%7}, {%8,%9}, {%0,%1,%2,%3};"
        : "+f"(d[0]), "+f"(d[1]), "+f"(d[2]), "+f"(d[3])
        : "r"(a[0]), "r"(a[1]), "r"(a[2]), "r"(a[3]), "r"(b[0]), "r"(b[1]));
}
__device__ __forceinline__ uint32_t pack_h2(__half a, __half b) {
    return ((uint32_t)__half_as_ushort(b) << 16) | (uint32_t)__half_as_ushort(a);
}
__device__ __forceinline__ float silu_mul(float h, float g) {
    return h * (g / (1.f + __expf(-g)));
}

// SMEM: rows_s[64] ints @0; stages @512.
// Stage (K-chunk 64): A [64m][64k] pitch 144 | B [64k][128n] pitch 272. 2 stages.
#define A_PITCH  144
#define B_PITCH  272
#define OFF_A    0
#define OFF_B    (64 * A_PITCH)
#define STAGE_SZ (64 * A_PITCH + 64 * B_PITCH)      // 26624
#define NSTAGE   2
#define SMEM_DYN (512 + NSTAGE * STAGE_SZ)          // 53760 (x4 CTAs = 215KB/SM)
#define KCH      64
#define NITER    (D_DIM / KCH)                      // 16 (same for H_DIM)
#define NTHREADS 128

// ---------------------------------------------------------------------------
// Kernel 0: bucket pairs by expert (single CTA)
// ---------------------------------------------------------------------------
__global__ void bucket_kernel(const int* __restrict__ expert_idxs) {
    __shared__ int scnt[E_NUM];
    __shared__ int soff[E_NUM];
    __shared__ int spos[E_NUM];
    int tid = threadIdx.x;
    if (tid < E_NUM) scnt[tid] = 0;
    __syncthreads();
    for (int i = tid; i < NPAIR; i += blockDim.x)
        atomicAdd(&scnt[expert_idxs[i]], 1);
    __syncthreads();
    if (tid == 0) {
        int s = 0;
        for (int e = 0; e < E_NUM; e++) { soff[e] = s; spos[e] = s; s += scnt[e]; }
    }
    __syncthreads();
    for (int i = tid; i < NPAIR; i += blockDim.x) {
        int e = expert_idxs[i];
        int pos = atomicAdd(&spos[e], 1);
        g_pairs[pos] = i;
    }
    __syncthreads();
    if (tid < E_NUM) { g_cnt[tid] = scnt[tid]; g_off[tid] = soff[tid]; }
}

// ---------------------------------------------------------------------------
// Kernel 1: zero the output (poisoned by harness; atomics accumulate into it)
// ---------------------------------------------------------------------------
__global__ void zero_out_kernel(float* __restrict__ out) {
    int q = blockIdx.x * blockDim.x + threadIdx.x;
    ((float4*)out)[q] = make_float4(0.f, 0.f, 0.f, 0.f);
}

// ---------------------------------------------------------------------------
// Kernel 2: fused fp32->fp16 conversion of x, W1, W2 (8 floats / thread)
// ---------------------------------------------------------------------------
#define X8   (NTOK * D_DIM / 8)
#define W18  (E_NUM * D_DIM * H2 / 8)
#define W28  (E_NUM * H_DIM * D_DIM / 8)
#define CONV_TOTAL (X8 + W18 + W28)

__global__ void conv_all_kernel(const float* __restrict__ x,
                                const float* __restrict__ W1,
                                const float* __restrict__ W2) {
    int idx = blockIdx.x * blockDim.x + threadIdx.x;
    const float4* src;
    __half* dst;
    if (idx < X8) {
        src = (const float4*)x + (size_t)idx * 2;
        dst = g_x + (size_t)idx * 8;
    } else if (idx < X8 + W18) {
        int j = idx - X8;
        src = (const float4*)W1 + (size_t)j * 2;
        dst = g_w1_hi + (size_t)j * 8;
    } else {
        int j = idx - (X8 + W18);
        src = (const float4*)W2 + (size_t)j * 2;
        dst = g_w2_hi + (size_t)j * 8;
    }
    float4 a = src[0], b = src[1];
    uint4 o;
    o.x = pack_h2(__float2half_rn(a.x), __float2half_rn(a.y));
    o.y = pack_h2(__float2half_rn(a.z), __float2half_rn(a.w));
    o.z = pack_h2(__float2half_rn(b.x), __float2half_rn(b.y));
    o.w = pack_h2(__float2half_rn(b.z), __float2half_rn(b.w));
    *(uint4*)dst = o;
}

// ---------------------------------------------------------------------------
// GEMM1 (mma.sync fp16, 4 warps/CTA, occ=4, warp tile 32x64): act = h*silu(g)
//   CTA 64m x (64h + 64g cols). 4 warps = wm(2) x wc(2); warp 32m x (32h+32g).
//   grid = (H/64, NPAIR/64, E)
// ---------------------------------------------------------------------------
__global__ void __launch_bounds__(NTHREADS, 4) gemm1_mma() {
    extern __shared__ char smem[];
    const int e   = blockIdx.z;
    const int bn  = blockIdx.x;
    const int bm  = blockIdx.y;
    const int cnt = g_cnt[e];
    if (bm * 64 >= cnt) return;
    const int off = g_off[e];
    const int tid = threadIdx.x;
    const int wid = tid >> 5;
    const int l   = tid & 31;
    const int wm  = wid >> 1;    // 0..1: 32 rows each
    const int wc  = wid & 1;     // 0..1: 32 h-cols + 32 g-cols each

    int* rows_s = (int*)smem;
    const uint32_t sbase = smem_u32(smem) + 512;

    if (tid < 64) {
        int m = bm * 64 + tid;
        rows_s[tid] = (m < cnt) ? (g_pairs[off + m] >> 1) : 0;
    }
    __syncthreads();

    uint32_t a_base[2];
#pragma unroll
    for (int mt = 0; mt < 2; mt++)
        a_base[mt] = (wm * 32 + mt * 16 + (l & 15)) * A_PITCH + (l >> 4) * 16;
    // p=0,1: h cols; p=2,3: g cols (within 128-wide B tile: 0-63 h, 64-127 g)
    uint32_t b_base[4];
#pragma unroll
    for (int p = 0; p < 4; p++) {
        int colbase = (p < 2) ? (wc * 32 + p * 16) : (64 + wc * 32 + (p - 2) * 16);
        b_base[p] = (l & 15) * B_PITCH + (colbase + (l >> 4) * 8) * 2;
    }

    float acc[2][8][4];
#pragma unroll
    for (int mt = 0; mt < 2; mt++)
#pragma unroll
        for (int nt = 0; nt < 8; nt++)
#pragma unroll
            for (int i = 0; i < 4; i++) acc[mt][nt][i] = 0.f;

    auto load_stage = [&](int c, int buf) {
        const int kt = c * KCH;
        const uint32_t st = sbase + buf * STAGE_SZ;
        // A: 64 rows x 128B = 512 cp16 / 128 thr = 4
#pragma unroll
        for (int i = 0; i < 4; i++) {
            int q = tid + i * NTHREADS;
            int r = q >> 3, ch = q & 7;
            cp16(st + OFF_A + r * A_PITCH + ch * 16,
                 g_x + (size_t)rows_s[r] * D_DIM + kt + ch * 8);
        }
        // B: 64 k-rows x 256B = 1024 cp16 / 128 thr = 8; ch<8 -> h, ch>=8 -> g
#pragma unroll
        for (int i = 0; i < 8; i++) {
            int q = tid + i * NTHREADS;
            int r = q >> 4, ch = q & 15;
            int gcol = (ch < 8) ? (bn * 64 + ch * 8) : (H_DIM + bn * 64 + (ch - 8) * 8);
            cp16(st + OFF_B + r * B_PITCH + ch * 16,
                 g_w1_hi + ((size_t)e * D_DIM + kt + r) * H2 + gcol);
        }
        CP_COMMIT();
    };

    load_stage(0, 0);

    for (int c = 0; c < NITER; c++) {
        CP_WAIT(0);
        __syncthreads();
        if (c + 1 < NITER) load_stage(c + 1, (c + 1) & 1);
        const uint32_t st = sbase + (c & 1) * STAGE_SZ;
#pragma unroll
        for (int kk = 0; kk < 4; kk++) {
            uint32_t ah[2][4], bf[4][4];
#pragma unroll
            for (int mt = 0; mt < 2; mt++)
                ldsm4(ah[mt], st + OFF_A + a_base[mt] + kk * 32);
#pragma unroll
            for (int p = 0; p < 4; p++)
                ldsm4t(bf[p], st + OFF_B + b_base[p] + kk * (16 * B_PITCH));
#pragma unroll
            for (int mt = 0; mt < 2; mt++)
#pragma unroll
                for (int nt = 0; nt < 8; nt++)
                    mma16816(acc[mt][nt], ah[mt], &bf[nt >> 1][(nt & 1) * 2]);
        }
    }

    // ---- epilogue: pair h (nt) with g (nt+4), SiLU-GLU, store fp16 ----
#pragma unroll
    for (int mt = 0; mt < 2; mt++) {
        int m0 = bm * 64 + wm * 32 + mt * 16 + (l >> 2);
        int m1 = m0 + 8;
        bool v0 = (m0 < cnt), v1 = (m1 < cnt);
        size_t row0 = (size_t)(off + m0) * H_DIM;
        size_t row1 = (size_t)(off + m1) * H_DIM;
#pragma unroll
        for (int nt = 0; nt < 4; nt++) {
            int col = bn * 64 + wc * 32 + nt * 8 + 2 * (l & 3);
            float a0 = silu_mul(acc[mt][nt][0], acc[mt][nt + 4][0]);
            float a1 = silu_mul(acc[mt][nt][1], acc[mt][nt + 4][1]);
            float a2 = silu_mul(acc[mt][nt][2], acc[mt][nt + 4][2]);
            float a3 = silu_mul(acc[mt][nt][3], acc[mt][nt + 4][3]);
            if (v0)
                *(uint32_t*)(g_act + row0 + col) =
                    pack_h2(__float2half_rn(a0), __float2half_rn(a1));
            if (v1)
                *(uint32_t*)(g_act + row1 + col) =
                    pack_h2(__float2half_rn(a2), __float2half_rn(a3));
        }
    }
}

// ---------------------------------------------------------------------------
// GEMM2 (mma.sync fp16, 4 warps/CTA, occ=4, warp tile 32x64): out += (act@W2)*p
//   CTA 64m x 128n. grid = (D/128, NPAIR/64, E). Atomic accumulate (2/elem).
// ---------------------------------------------------------------------------
__global__ void __launch_bounds__(NTHREADS, 4) gemm2_mma(const float* __restrict__ expert_p,
                                                         float* __restrict__ out) {
    extern __shared__ char smem[];
    const int e   = blockIdx.z;
    const int bn  = blockIdx.x;
    const int bm  = blockIdx.y;
    const int cnt = g_cnt[e];
    if (bm * 64 >= cnt) return;
    const int off = g_off[e];
    const int tid = threadIdx.x;
    const int wid = tid >> 5;
    const int l   = tid & 31;
    const int wm  = wid >> 1;
    const int wc  = wid & 1;

    const uint32_t sbase = smem_u32(smem) + 512;

    uint32_t a_base[2];
#pragma unroll
    for (int mt = 0; mt < 2; mt++)
        a_base[mt] = (wm * 32 + mt * 16 + (l & 15)) * A_PITCH + (l >> 4) * 16;
    uint32_t b_base[4];
#pragma unroll
    for (int p = 0; p < 4; p++) {
        int colbase = wc * 64 + p * 16;
        b_base[p] = (l & 15) * B_PITCH + (colbase + (l >> 4) * 8) * 2;
    }

    float acc[2][8][4];
#pragma unroll
    for (int mt = 0; mt < 2; mt++)
#pragma unroll
        for (int nt = 0; nt < 8; nt++)
#pragma unroll
            for (int i = 0; i < 4; i++) acc[mt][nt][i] = 0.f;

    auto load_stage = [&](int c, int buf) {
        const int kt = c * KCH;
        const uint32_t st = sbase + buf * STAGE_SZ;
#pragma unroll
        for (int i = 0; i < 4; i++) {
            int q = tid + i * NTHREADS;
            int r = q >> 3, ch = q & 7;
            int gr = off + bm * 64 + r;
            if (gr > NPAIR - 1) gr = NPAIR - 1;
            cp16(st + OFF_A + r * A_PITCH + ch * 16,
                 g_act + (size_t)gr * H_DIM + kt + ch * 8);
        }
#pragma unroll
        for (int i = 0; i < 8; i++) {
            int q = tid + i * NTHREADS;
            int r = q >> 4, ch = q & 15;
            cp16(st + OFF_B + r * B_PITCH + ch * 16,
                 g_w2_hi + ((size_t)e * H_DIM + kt + r) * D_DIM + bn * 128 + ch * 8);
        }
        CP_COMMIT();
    };

    load_stage(0, 0);

    for (int c = 0; c < NITER; c++) {
        CP_WAIT(0);
        __syncthreads();
        if (c + 1 < NITER) load_stage(c + 1, (c + 1) & 1);
        const uint32_t st = sbase + (c & 1) * STAGE_SZ;
#pragma unroll
        for (int kk = 0; kk < 4; kk++) {
            uint32_t ah[2][4], bf[4][4];
#pragma unroll
            for (int mt = 0; mt < 2; mt++)
                ldsm4(ah[mt], st + OFF_A + a_base[mt] + kk * 32);
#pragma unroll
            for (int p = 0; p < 4; p++)
                ldsm4t(bf[p], st + OFF_B + b_base[p] + kk * (16 * B_PITCH));
#pragma unroll
            for (int mt = 0; mt < 2; mt++)
#pragma unroll
                for (int nt = 0; nt < 8; nt++)
                    mma16816(acc[mt][nt], ah[mt], &bf[nt >> 1][(nt & 1) * 2]);
        }
    }

    // ---- epilogue: scale by gate prob, atomically accumulate into out ----
#pragma unroll
    for (int mt = 0; mt < 2; mt++) {
        int m0 = bm * 64 + wm * 32 + mt * 16 + (l >> 2);
        int m1 = m0 + 8;
        bool v0 = (m0 < cnt), v1 = (m1 < cnt);
        int   pid0 = 0, pid1 = 0;
        float pv0 = 0.f, pv1 = 0.f;
        if (v0) { pid0 = g_pairs[off + m0]; pv0 = expert_p[pid0]; }
        if (v1) { pid1 = g_pairs[off + m1]; pv1 = expert_p[pid1]; }
        float* dst0 = out + (size_t)(pid0 >> 1) * D_DIM;
        float* dst1 = out + (size_t)(pid1 >> 1) * D_DIM;
#pragma unroll
        for (int nt = 0; nt < 8; nt++) {
            int col = bn * 128 + wc * 64 + nt * 8 + 2 * (l & 3);
            if (v0) {
                atomicAdd(dst0 + col,     acc[mt][nt][0] * pv0);
                atomicAdd(dst0 + col + 1, acc[mt][nt][1] * pv0);
            }
            if (v1) {
                atomicAdd(dst1 + col,     acc[mt][nt][2] * pv1);
                atomicAdd(dst1 + col + 1, acc[mt][nt][3] * pv1);
            }
        }
    }
}

// ---------------------------------------------------------------------------
extern "C" void kernel_launch(void* const* d_in, const int* in_sizes, int n_in,
                              void* d_out, int out_size) {
    const float* x    = (const float*)d_in[0];
    const float* ep   = (const float*)d_in[1];
    const int*   eidx = (const int*)  d_in[2];
    const float* W1   = (const float*)d_in[3];
    const float* W2   = (const float*)d_in[4];
    float*       out  = (float*)d_out;

    cudaFuncSetAttribute(gemm1_mma, cudaFuncAttributeMaxDynamicSharedMemorySize, SMEM_DYN);
    cudaFuncSetAttribute(gemm2_mma, cudaFuncAttributeMaxDynamicSharedMemorySize, SMEM_DYN);

    bucket_kernel<<<1, 512>>>(eidx);
    zero_out_kernel<<<(NTOK * D_DIM / 4) / 256, 256>>>(out);

    conv_all_kernel<<<CONV_TOTAL / 256, 256>>>(x, W1, W2);

    dim3 g1(H_DIM / 64, NPAIR / 64, E_NUM);     // (16, 64, 8)
    gemm1_mma<<<g1, NTHREADS, SMEM_DYN>>>();

    dim3 g2(D_DIM / 128, NPAIR / 64, E_NUM);    // (8, 64, 8)
    gemm2_mma<<<g2, NTHREADS, SMEM_DYN>>>(ep, out);
}